// round 1
// baseline (speedup 1.0000x reference)
#include <cuda_runtime.h>
#include <cuda_fp16.h>
#include <mma.h>

using namespace nvcuda;

// ---------------------------------------------------------------------------
// LinearRNN as a truncated convolution.
//   y_t = sum_{m=0}^{K-1} H_m u_{t-m} + C A^t x0 (t<K)
//   H_0 = D, H_m = C A^{m-1} B.  Spectral radius of A ~= 0.8 -> tail at K=96
//   is ~5e-10, far below the 1e-3 tolerance.
// ---------------------------------------------------------------------------

#define KWIN     96                  // convolution window (multiple of 16)
#define TB       256                 // output rows per block
#define NTHREADS 256                 // 8 warps
#define UROWS    (TB + KWIN - 1)     // 351 u rows staged in smem
#define USTRIDE  72                  // padded half stride
#define HSTRIDE  72

// Scratch (static device globals; no runtime allocation).
__device__ float  g_P[KWIN * 64 * 64];   // A^m, m = 0..K-1 (P_0 = I)
__device__ __half g_HT[KWIN * 64 * 64];  // HT_m[j][p] = H_m[p][j] (fp16)
__device__ float  g_s[KWIN * 64];        // s_t = C A^t x0

// ---------------------------------------------------------------------------
// Setup kernels
// ---------------------------------------------------------------------------

__global__ void init_P(const float* __restrict__ A) {
    int idx = blockIdx.x * blockDim.x + threadIdx.x;
    if (idx < 4096) {
        int r = idx / 64, c = idx % 64;
        g_P[idx] = (r == c) ? 1.0f : 0.0f;       // P_0 = I
    } else if (idx < 8192) {
        g_P[idx] = A[idx - 4096];                // P_1 = A
    }
}

// Doubling level: given powers 1..c, block i computes P_{c+i} = P_c @ P_i.
__global__ void mm_power(int c) {
    __shared__ float As[64 * 64];
    __shared__ float Bs[64 * 64];
    int i   = blockIdx.x + 1;
    int tgt = c + i;
    if (tgt >= KWIN) return;
    const float* Am = g_P + (size_t)c * 4096;
    const float* Bm = g_P + (size_t)i * 4096;
    for (int k = threadIdx.x; k < 4096; k += blockDim.x) {
        As[k] = Am[k];
        Bs[k] = Bm[k];
    }
    __syncthreads();
    int r = threadIdx.x / 4, cg = threadIdx.x % 4;
    float acc[16];
#pragma unroll
    for (int cc = 0; cc < 16; cc++) acc[cc] = 0.0f;
    for (int k = 0; k < 64; k++) {
        float a = As[r * 64 + k];
#pragma unroll
        for (int cc = 0; cc < 16; cc++)
            acc[cc] += a * Bs[k * 64 + cg * 16 + cc];
    }
    float* O = g_P + (size_t)tgt * 4096;
#pragma unroll
    for (int cc = 0; cc < 16; cc++) O[r * 64 + cg * 16 + cc] = acc[cc];
}

// Block m: HT_m = (C @ P_{m-1} @ B)^T   (m=0 -> D^T), stored fp16.
__global__ void make_H(const float* __restrict__ B,
                       const float* __restrict__ C,
                       const float* __restrict__ D) {
    int m = blockIdx.x;
    __shared__ float S1[64 * 64];
    __shared__ float S2[64 * 64];
    int tid = threadIdx.x;

    if (m == 0) {
        for (int k = tid; k < 4096; k += blockDim.x) {
            int p = k / 64, j = k % 64;
            g_HT[(size_t)j * 64 + p] = __float2half_rn(D[(size_t)p * 64 + j]);
        }
        return;
    }

    const float* P = g_P + (size_t)(m - 1) * 4096;
    for (int k = tid; k < 4096; k += blockDim.x) {
        S1[k] = C[k];
        S2[k] = P[k];
    }
    __syncthreads();

    int r = tid / 4, cg = tid % 4;
    float t1[16];
#pragma unroll
    for (int cc = 0; cc < 16; cc++) t1[cc] = 0.0f;
    for (int k = 0; k < 64; k++) {
        float a = S1[r * 64 + k];
#pragma unroll
        for (int cc = 0; cc < 16; cc++)
            t1[cc] += a * S2[k * 64 + cg * 16 + cc];   // T1 = C @ P_{m-1}
    }
    __syncthreads();
#pragma unroll
    for (int cc = 0; cc < 16; cc++) S1[r * 64 + cg * 16 + cc] = t1[cc];
    for (int k = tid; k < 4096; k += blockDim.x) S2[k] = B[k];
    __syncthreads();

    float h[16];
#pragma unroll
    for (int cc = 0; cc < 16; cc++) h[cc] = 0.0f;
    for (int k = 0; k < 64; k++) {
        float a = S1[r * 64 + k];
#pragma unroll
        for (int cc = 0; cc < 16; cc++)
            h[cc] += a * S2[k * 64 + cg * 16 + cc];    // H = T1 @ B
    }
    __half* HT = g_HT + (size_t)m * 4096;
#pragma unroll
    for (int cc = 0; cc < 16; cc++) {
        int j = cg * 16 + cc;
        HT[(size_t)j * 64 + r] = __float2half_rn(h[cc]);  // transpose
    }
}

// Block t: s_t = C (P_t x0)
__global__ void make_s(const float* __restrict__ x0,
                       const float* __restrict__ C) {
    int t = blockIdx.x;
    __shared__ float v[64];
    __shared__ float xs[64];
    int i = threadIdx.x;
    xs[i] = x0[i];
    __syncthreads();
    const float* P = g_P + (size_t)t * 4096;
    float acc = 0.0f;
    for (int n = 0; n < 64; n++) acc += P[i * 64 + n] * xs[n];
    v[i] = acc;
    __syncthreads();
    float s = 0.0f;
    for (int n = 0; n < 64; n++) s += C[i * 64 + n] * v[n];
    g_s[t * 64 + i] = s;
}

__global__ void add_s(float* __restrict__ y) {
    int idx = blockIdx.x * 64 + threadIdx.x;
    y[idx] += g_s[idx];
}

// ---------------------------------------------------------------------------
// Main convolution GEMM.
// Block handles TB=256 consecutive t rows x all 64 output cols.
// u window (TB+K-1 rows) staged fp32->fp16 in smem; H_m streamed per-m.
// Warp w owns rows [w*32, w*32+32): 2 row tiles x 4 col tiles of 16x16 acc.
// ---------------------------------------------------------------------------
__global__ __launch_bounds__(NTHREADS)
void conv_main(const float* __restrict__ u, float* __restrict__ y, int T) {
    extern __shared__ __half sm[];
    __half* us = sm;                           // [UROWS][USTRIDE]
    __half* hs = sm + UROWS * USTRIDE;         // [64][HSTRIDE]

    const int t0 = blockIdx.x * TB;

    // Stage u window (zero-padded below t=0), converting fp32 -> fp16.
    const int nv = UROWS * 16;                 // float4 chunks (16 per row)
    for (int idx = threadIdx.x; idx < nv; idx += NTHREADS) {
        int r  = idx >> 4;
        int c4 = (idx & 15) << 2;
        int t  = t0 - (KWIN - 1) + r;
        __half2 h01, h23;
        if ((unsigned)t < (unsigned)T) {
            const float4 v = *reinterpret_cast<const float4*>(u + (size_t)t * 64 + c4);
            h01 = __floats2half2_rn(v.x, v.y);
            h23 = __floats2half2_rn(v.z, v.w);
        } else {
            h01 = __half2half2(__float2half_rn(0.0f));
            h23 = h01;
        }
        __half2* dst = reinterpret_cast<__half2*>(us + r * USTRIDE + c4);
        dst[0] = h01;
        dst[1] = h23;
    }

    wmma::fragment<wmma::accumulator, 16, 16, 16, float> acc[2][4];
#pragma unroll
    for (int a = 0; a < 2; a++)
#pragma unroll
        for (int b = 0; b < 4; b++) wmma::fill_fragment(acc[a][b], 0.0f);

    const int w    = threadIdx.x >> 5;
    const int trow = w * 32;

    for (int m = 0; m < KWIN; m++) {
        __syncthreads();  // previous hs fully consumed (also covers u staging)
        const __half* Hm = g_HT + (size_t)m * 4096;
        for (int idx = threadIdx.x; idx < 512; idx += NTHREADS) {  // 512 x uint4
            int j  = idx >> 3;
            int p8 = (idx & 7) << 3;
            *reinterpret_cast<uint4*>(hs + j * HSTRIDE + p8) =
                *reinterpret_cast<const uint4*>(Hm + j * 64 + p8);
        }
        __syncthreads();

#pragma unroll
        for (int j0 = 0; j0 < 64; j0 += 16) {
            wmma::fragment<wmma::matrix_b, 16, 16, 16, __half, wmma::row_major> fb[4];
#pragma unroll
            for (int n = 0; n < 4; n++)
                wmma::load_matrix_sync(fb[n], hs + j0 * HSTRIDE + n * 16, HSTRIDE);
#pragma unroll
            for (int tr = 0; tr < 2; tr++) {
                wmma::fragment<wmma::matrix_a, 16, 16, 16, __half, wmma::row_major> fa;
                int lr = trow + tr * 16 + (KWIN - 1) - m;
                wmma::load_matrix_sync(fa, us + lr * USTRIDE + j0, USTRIDE);
#pragma unroll
                for (int n = 0; n < 4; n++)
                    wmma::mma_sync(acc[tr][n], fa, fb[n], acc[tr][n]);
            }
        }
    }

#pragma unroll
    for (int tr = 0; tr < 2; tr++)
#pragma unroll
        for (int n = 0; n < 4; n++)
            wmma::store_matrix_sync(y + (size_t)(t0 + trow + tr * 16) * 64 + n * 16,
                                    acc[tr][n], 64, wmma::mem_row_major);
}

// ---------------------------------------------------------------------------
extern "C" void kernel_launch(void* const* d_in, const int* in_sizes, int n_in,
                              void* d_out, int out_size) {
    const float* u  = (const float*)d_in[0];
    const float* x0 = (const float*)d_in[1];
    const float* A  = (const float*)d_in[2];
    const float* B  = (const float*)d_in[3];
    const float* C  = (const float*)d_in[4];
    const float* D  = (const float*)d_in[5];
    float* y = (float*)d_out;

    int T = in_sizes[0] / 64;

    cudaFuncSetAttribute(conv_main, cudaFuncAttributeMaxDynamicSharedMemorySize,
                         (UROWS * USTRIDE + 64 * HSTRIDE) * (int)sizeof(__half));

    // Setup: powers of A (log-depth doubling), Markov parameters, x0 transient.
    init_P<<<32, 256>>>(A);
    for (int c = 1; c < KWIN - 1; c *= 2)
        mm_power<<<c, 256>>>(c);
    make_H<<<KWIN, 256>>>(B, C, D);
    make_s<<<KWIN, 64>>>(x0, C);

    // Main convolution GEMM + x0 transient correction.
    size_t smem = (UROWS * USTRIDE + 64 * HSTRIDE) * sizeof(__half);
    conv_main<<<T / TB, NTHREADS, smem>>>(u, y, T);
    add_s<<<KWIN, 64>>>(y);
}

// round 3
// speedup vs baseline: 2.0472x; 2.0472x over previous
#include <cuda_runtime.h>
#include <cuda_fp16.h>
#include <mma.h>
#include <cstdint>

using namespace nvcuda;

// ---------------------------------------------------------------------------
// LinearRNN via two-stage chunked factorization (L=16, K=64 truncation).
//   Stage 1: chunk-start states  Xs[c] = sum_{m<64} (A^m B) u[16c-1-m]  (+x0 fix)
//   Stage 2: Y[c, 64*dt+p] = sum_{s<=dt} H'_{dt-s} u[16c+s] + (C A^dt) Xs[c]
//            as ONE dense GEMM  [NC x 1088] @ [1088 x 1024]
// All tensor work on baseline wmma (HMMA) + cp.async; no sm_103a-only instrs
// (harness compiles through compute_103 virtual arch -> tcgen05 unavailable).
// ---------------------------------------------------------------------------

#define LCH 16                 // chunk length
#define KTAP 64                // stage-1 truncation taps

// ------------------------- static device scratch ---------------------------
__device__ float  g_Pw[64 * 4096];          // A^q, q=0..63
__device__ float  g_Mx[64 * 4096];          // A^q B, q=0..63
__device__ float  g_Hp[16 * 4096];          // H'_m (H'_0=D, H'_m=C A^{m-1} B)
__device__ float  g_G [16 * 4096];          // G_dt = C A^dt
__device__ float  g_xfix[4 * 64];           // A^{16c} x0, c=0..3
__device__ __half g_Wx[4096 * 64];          // stage-1 weights
__device__ __half g_Wy[1088 * 1024];        // stage-2 weights
__device__ __half g_Xs[16384 * 64];         // chunk-start states (fp16)
__device__ __half g_u16[262144 * 64];       // u converted to fp16

// ------------------------------ helpers ------------------------------------
__device__ __forceinline__ uint32_t smem_addr(const void* p) {
    return (uint32_t)__cvta_generic_to_shared(p);
}
#define CP16(dst, src) \
    asm volatile("cp.async.cg.shared.global [%0], [%1], 16;" :: "r"(dst), "l"(src))
#define CP_COMMIT() asm volatile("cp.async.commit_group;" ::: "memory")
#define CP_WAIT1()  asm volatile("cp.async.wait_group 1;" ::: "memory")
#define CP_WAIT0()  asm volatile("cp.async.wait_group 0;" ::: "memory")

// 64x64x64 fp32 matmul, one block of 256 threads, 4x4 register tiles.
__device__ void mm64(const float* __restrict__ X, const float* __restrict__ Y,
                     float* __restrict__ O, float* Sx, float* Sy) {
    int tid = threadIdx.x;
    for (int k = tid; k < 4096; k += 256) { Sx[k] = X[k]; Sy[k] = Y[k]; }
    __syncthreads();
    int r0 = (tid >> 4) << 2, c0 = (tid & 15) << 2;
    float acc[4][4] = {};
    for (int k = 0; k < 64; k++) {
        float4 b = *(const float4*)&Sy[k * 64 + c0];
#pragma unroll
        for (int i = 0; i < 4; i++) {
            float a = Sx[(r0 + i) * 64 + k];
            acc[i][0] += a * b.x; acc[i][1] += a * b.y;
            acc[i][2] += a * b.z; acc[i][3] += a * b.w;
        }
    }
#pragma unroll
    for (int i = 0; i < 4; i++)
#pragma unroll
        for (int j = 0; j < 4; j++)
            O[(r0 + i) * 64 + c0 + j] = acc[i][j];
}

// ------------------------------ setup --------------------------------------
__global__ void prepass_u16(const float* __restrict__ u) {
    int idx = (blockIdx.x * 256 + threadIdx.x) * 8;
    float4 a = *(const float4*)(u + idx);
    float4 b = *(const float4*)(u + idx + 4);
    __half2 h0 = __floats2half2_rn(a.x, a.y), h1 = __floats2half2_rn(a.z, a.w);
    __half2 h2 = __floats2half2_rn(b.x, b.y), h3 = __floats2half2_rn(b.z, b.w);
    uint4 pk;
    pk.x = *(uint32_t*)&h0; pk.y = *(uint32_t*)&h1;
    pk.z = *(uint32_t*)&h2; pk.w = *(uint32_t*)&h3;
    *(uint4*)(g_u16 + idx) = pk;
}

__global__ void setup_init(const float* __restrict__ A, const float* __restrict__ B) {
    int b = blockIdx.x;
    for (int k = threadIdx.x; k < 4096; k += 256) {
        if (b == 0)      g_Pw[k] = ((k / 64) == (k % 64)) ? 1.0f : 0.0f; // P_0 = I
        else if (b == 1) g_Pw[4096 + k] = A[k];                          // P_1 = A
        else             g_Mx[k] = B[k];                                 // Mx_0 = B
    }
}

// Level c: blocks [0,c): P_{c+1+b} = P_c P_{1+b};  [c,2c): Mx_{c+(b-c)} = P_c Mx_{b-c}
__global__ void setup_level(int c) {
    __shared__ float Sx[4096], Sy[4096];
    int b = blockIdx.x;
    if (b < c) {
        int tgt = c + b + 1;
        if (tgt >= 64) return;
        mm64(g_Pw + (size_t)c * 4096, g_Pw + (size_t)(b + 1) * 4096,
             g_Pw + (size_t)tgt * 4096, Sx, Sy);
    } else {
        int i = b - c, tgt = c + i;
        if (tgt >= 64) return;
        mm64(g_Pw + (size_t)c * 4096, g_Mx + (size_t)i * 4096,
             g_Mx + (size_t)tgt * 4096, Sx, Sy);
    }
}

// H'_m, G_dt, Wx transpose-convert, x0 fixups
__global__ void setup_finalize(const float* __restrict__ C,
                               const float* __restrict__ D,
                               const float* __restrict__ x0) {
    __shared__ float Sx[4096], Sy[4096];
    int b = blockIdx.x, tid = threadIdx.x;
    if (b == 0) {
        for (int k = tid; k < 4096; k += 256) g_Hp[k] = D[k];
    } else if (b < 16) {
        mm64(C, g_Mx + (size_t)(b - 1) * 4096, g_Hp + (size_t)b * 4096, Sx, Sy);
    } else if (b < 32) {
        int dt = b - 16;
        mm64(C, g_Pw + (size_t)dt * 4096, g_G + (size_t)dt * 4096, Sx, Sy);
    } else if (b < 96) {
        int q = b - 32;
        const float* M = g_Mx + (size_t)(63 - q) * 4096;
        for (int idx = tid; idx < 4096; idx += 256) {
            int j = idx >> 6, n = idx & 63;
            g_Wx[(size_t)(q * 64 + j) * 64 + n] = __float2half_rn(M[n * 64 + j]);
        }
    } else {
        // xfix[c][n] = (A^{16c} x0)[n], c = 0..3
        if (tid < 256) {
            int c = tid >> 6, n = tid & 63;
            const float* P = g_Pw + (size_t)(16 * c) * 4096;
            float acc = 0.0f;
            for (int k = 0; k < 64; k++) acc += P[n * 64 + k] * x0[k];
            g_xfix[c * 64 + n] = acc;
        }
    }
}

__global__ void setup_scatter() {
    int b = blockIdx.x, tid = threadIdx.x;
    if (b < 256) {
        int s = b >> 4, dt = b & 15;
        const float* H = g_Hp + (size_t)(dt - s) * 4096;
        for (int idx = tid; idx < 4096; idx += 256) {
            int j = idx >> 6, p = idx & 63;
            __half v = (dt >= s) ? __float2half_rn(H[p * 64 + j]) : __half(0.0f);
            g_Wy[(size_t)(64 * s + j) * 1024 + 64 * dt + p] = v;
        }
    } else {
        int dt = b - 256;
        const float* G = g_G + (size_t)dt * 4096;
        for (int idx = tid; idx < 4096; idx += 256) {
            int n = idx >> 6, p = idx & 63;
            g_Wy[(size_t)(1024 + n) * 1024 + 64 * dt + p] = __float2half_rn(G[p * 64 + n]);
        }
    }
}

// ------------------------------ stage 1 ------------------------------------
// Xs[NC,64] = Uwin[NC,4096] @ Wx[4096,64]; CTA = 128 chunk-rows. 64 k-iters.
__global__ __launch_bounds__(256)
void stage1(int NC) {
    extern __shared__ __half smh[];
    __half* As[2] = { smh, smh + 9216 };               // [128][72]
    __half* Bs[2] = { smh + 18432, smh + 18432 + 4608 }; // [64][72]
    const int tid = threadIdx.x;
    const int c0 = blockIdx.x * 128;
    const uint4 zero4 = make_uint4(0, 0, 0, 0);

    auto load = [&](int bf, int q) {
        for (int idx = tid; idx < 1024; idx += 256) {          // A tile
            int i = idx >> 3, cc = idx & 7;
            int t = 16 * (c0 + i) - KTAP + q;
            __half* d = As[bf] + i * 72 + cc * 8;
            if (t < 0) *(uint4*)d = zero4;
            else CP16(smem_addr(d), g_u16 + (size_t)t * 64 + cc * 8);
        }
        for (int idx = tid; idx < 512; idx += 256) {           // B tile (Wx block q)
            int j = idx >> 3, cc = idx & 7;
            CP16(smem_addr(Bs[bf] + j * 72 + cc * 8),
                 g_Wx + (size_t)(q * 64 + j) * 64 + cc * 8);
        }
        CP_COMMIT();
    };

    const int w = tid >> 5;
    wmma::fragment<wmma::accumulator, 16, 16, 16, float> acc[4];
#pragma unroll
    for (int n = 0; n < 4; n++) wmma::fill_fragment(acc[n], 0.0f);

    load(0, 0);
    for (int it = 0; it < KTAP; it++) {
        if (it + 1 < KTAP) { load((it + 1) & 1, it + 1); CP_WAIT1(); }
        else CP_WAIT0();
        __syncthreads();
        const __half* Ab = As[it & 1];
        const __half* Bb = Bs[it & 1];
#pragma unroll
        for (int kk = 0; kk < 4; kk++) {
            wmma::fragment<wmma::matrix_a, 16, 16, 16, __half, wmma::row_major> fa;
            wmma::load_matrix_sync(fa, Ab + (w * 16) * 72 + kk * 16, 72);
#pragma unroll
            for (int n = 0; n < 4; n++) {
                wmma::fragment<wmma::matrix_b, 16, 16, 16, __half, wmma::row_major> fb;
                wmma::load_matrix_sync(fb, Bb + (kk * 16) * 72 + n * 16, 72);
                wmma::mma_sync(acc[n], fa, fb, acc[n]);
            }
        }
        __syncthreads();
    }

    // epilogue: frags -> smem f32 -> (+x0 fix) -> fp16 gmem
    float* smf = reinterpret_cast<float*>(smh);        // 128*64 f32 = 32KB
#pragma unroll
    for (int n = 0; n < 4; n++)
        wmma::store_matrix_sync(smf + (w * 16) * 64 + n * 16, acc[n], 64,
                                wmma::mem_row_major);
    __syncthreads();
    for (int idx = tid; idx < 8192; idx += 256) {
        int i = idx >> 6, n = idx & 63;
        int c = c0 + i;
        float v = smf[idx];
        if (c < 4) v += g_xfix[c * 64 + n];
        g_Xs[(size_t)c * 64 + n] = __float2half_rn(v);
    }
}

// ------------------------------ stage 2 ------------------------------------
// Y[NC,1024] = [u16 | Xs][NC,1088] @ Wy[1088,1024]; CTA = 128 rows x 128 cols.
__global__ __launch_bounds__(256)
void stage2(float* __restrict__ y, int NC) {
    extern __shared__ __half smh[];
    __half* As[2] = { smh, smh + 9216 };                  // [128][72]
    __half* Bs[2] = { smh + 18432, smh + 18432 + 8704 };  // [64][136]
    const int tid = threadIdx.x;
    const int mt = blockIdx.x >> 3, nt = blockIdx.x & 7;
    const int c0 = mt * 128, ncol0 = nt * 128;

    auto load = [&](int bf, int kt) {
        for (int idx = tid; idx < 1024; idx += 256) {      // A tile
            int i = idx >> 3, cc = idx & 7;
            const __half* src = (kt < 16)
                ? g_u16 + (size_t)(c0 + i) * 1024 + kt * 64 + cc * 8
                : g_Xs + (size_t)(c0 + i) * 64 + cc * 8;
            CP16(smem_addr(As[bf] + i * 72 + cc * 8), src);
        }
        for (int idx = tid; idx < 1024; idx += 256) {      // B tile
            int r = idx >> 4, cc = idx & 15;
            CP16(smem_addr(Bs[bf] + r * 136 + cc * 8),
                 g_Wy + (size_t)(kt * 64 + r) * 1024 + ncol0 + cc * 8);
        }
        CP_COMMIT();
    };

    const int w = tid >> 5;
    const int wr = w >> 1, wc = w & 1;                     // 4x2 warp grid
    wmma::fragment<wmma::accumulator, 16, 16, 16, float> acc[2][4];
#pragma unroll
    for (int tr = 0; tr < 2; tr++)
#pragma unroll
        for (int n = 0; n < 4; n++) wmma::fill_fragment(acc[tr][n], 0.0f);

    load(0, 0);
    for (int it = 0; it < 17; it++) {
        if (it + 1 < 17) { load((it + 1) & 1, it + 1); CP_WAIT1(); }
        else CP_WAIT0();
        __syncthreads();
        const __half* Ab = As[it & 1];
        const __half* Bb = Bs[it & 1];
#pragma unroll
        for (int kk = 0; kk < 4; kk++) {
            wmma::fragment<wmma::matrix_b, 16, 16, 16, __half, wmma::row_major> fb[4];
#pragma unroll
            for (int n = 0; n < 4; n++)
                wmma::load_matrix_sync(fb[n], Bb + (kk * 16) * 136 + wc * 64 + n * 16, 136);
#pragma unroll
            for (int tr = 0; tr < 2; tr++) {
                wmma::fragment<wmma::matrix_a, 16, 16, 16, __half, wmma::row_major> fa;
                wmma::load_matrix_sync(fa, Ab + (wr * 32 + tr * 16) * 72 + kk * 16, 72);
#pragma unroll
                for (int n = 0; n < 4; n++)
                    wmma::mma_sync(acc[tr][n], fa, fb[n], acc[tr][n]);
            }
        }
        __syncthreads();
    }

#pragma unroll
    for (int tr = 0; tr < 2; tr++)
#pragma unroll
        for (int n = 0; n < 4; n++)
            wmma::store_matrix_sync(
                y + (size_t)(c0 + wr * 32 + tr * 16) * 1024 + ncol0 + wc * 64 + n * 16,
                acc[tr][n], 1024, wmma::mem_row_major);
}

// ---------------------------------------------------------------------------
extern "C" void kernel_launch(void* const* d_in, const int* in_sizes, int n_in,
                              void* d_out, int out_size) {
    const float* u  = (const float*)d_in[0];
    const float* x0 = (const float*)d_in[1];
    const float* A  = (const float*)d_in[2];
    const float* B  = (const float*)d_in[3];
    const float* C  = (const float*)d_in[4];
    const float* D  = (const float*)d_in[5];
    float* y = (float*)d_out;

    const int T  = in_sizes[0] / 64;     // 262144
    const int NC = T / LCH;              // 16384

    static bool attr_set = false;
    if (!attr_set) {
        cudaFuncSetAttribute(stage1, cudaFuncAttributeMaxDynamicSharedMemorySize, 55296);
        cudaFuncSetAttribute(stage2, cudaFuncAttributeMaxDynamicSharedMemorySize, 71680);
        attr_set = true;
    }

    prepass_u16<<<T * 64 / 2048, 256>>>(u);
    setup_init<<<3, 256>>>(A, B);
    for (int c = 1; c < 64; c *= 2)             // 1,2,4,8,16,32
        setup_level<<<2 * c, 256>>>(c);
    setup_finalize<<<97, 256>>>(C, D, x0);
    setup_scatter<<<272, 256>>>();

    stage1<<<NC / 128, 256, 55296>>>(NC);
    stage2<<<(NC / 128) * 8, 256, 71680>>>(y, NC);
}